// round 13
// baseline (speedup 1.0000x reference)
#include <cuda_runtime.h>
#include <cuda_bf16.h>
#include <cstdint>

#define HW   16384
#define NB   2
#define CIN  128
#define CO   64
#define NK   64
#define NPIX (NB*HW)
#define GRIDN 129u
#define NT    512

// accumulator pack
#define ACC_SUMS  0        // 8192 floats: [b][k][o]
#define ACC_CNT   8192     // 128 floats:  [b][k]
#define ACC_BNSUM 8320     // 64
#define ACC_BNSQ  8384     // 64
#define ACCN      8448

// smem layout
// bytes: A tiles @1024 (hi 32KB, lo 32KB -> 64KB), B @66560 (hi 16KB, lo 16KB)
// floats: scnt @24832, sidx @24896 (256 ints), feat @25152
#define A_OFFB    1024
#define A_LOB     32768
#define B_OFFB    66560
#define B_LOB     16384
#define SCNT_OFF  24832
#define SIDX_OFF  24896
#define FEAT_OFF  25152
#define FEAT_STR  68
#define SMEM_FLOATS (FEAT_OFF + 256*FEAT_STR)    // 42560
#define SMEM_BYTES  (SMEM_FLOATS*4)              // 170240

// ---------------- scratch (static device globals; zero-initialized by loader) ----------------
__device__ float    g_acc[ACCN];
__device__ unsigned g_bar;                   // monotonic ticket barrier
__device__ float    g_invcov[CO*CO];
__device__ float    g_means[NB*NK*CO];
__device__ float    g_T[NB*NK*CO];
__device__ float    g_diag[NB*NK];
__device__ float    g_adjm[NB*NK*CO];

// ---------------- helpers ----------------
__device__ __forceinline__ unsigned smem_u32(const void* p) {
    unsigned a;
    asm("{ .reg .u64 t; cvta.to.shared.u64 t, %1; cvt.u32.u64 %0, t; }" : "=r"(a) : "l"(p));
    return a;
}
__device__ __forceinline__ void ldm4(uint32_t* r, unsigned addr) {
    asm volatile("ldmatrix.sync.aligned.m8n8.x4.trans.shared.b16 {%0,%1,%2,%3}, [%4];"
                 : "=r"(r[0]), "=r"(r[1]), "=r"(r[2]), "=r"(r[3]) : "r"(addr));
}
__device__ __forceinline__ void mma_bf16(float* c, const uint32_t* a, const uint32_t* bb) {
    asm volatile("mma.sync.aligned.m16n8k16.row.col.f32.bf16.bf16.f32 "
                 "{%0,%1,%2,%3}, {%4,%5,%6,%7}, {%8,%9}, {%0,%1,%2,%3};"
                 : "+f"(c[0]), "+f"(c[1]), "+f"(c[2]), "+f"(c[3])
                 : "r"(a[0]), "r"(a[1]), "r"(a[2]), "r"(a[3]), "r"(bb[0]), "r"(bb[1]));
}
__device__ __forceinline__ void red2(float* p, float a, float b) {
    asm volatile("red.add.v2.f32 [%0], {%1, %2};" :: "l"(p), "f"(a), "f"(b) : "memory");
}

// device-wide ticket barrier; all GRIDN blocks resident, monotonic across replays
__device__ __forceinline__ void gbar() {
    __threadfence();
    __syncthreads();
    if (threadIdx.x == 0) {
        unsigned t   = atomicAdd(&g_bar, 1u);
        unsigned tgt = (t / GRIDN + 1u) * GRIDN;
        unsigned v;
        for (;;) {
            asm volatile("ld.acquire.gpu.u32 %0, [%1];" : "=r"(v) : "l"(&g_bar) : "memory");
            if (v >= tgt) break;
            __nanosleep(32);
        }
    }
    __syncthreads();
}

// ---------------- the single fused kernel ----------------
__global__ __launch_bounds__(NT) void k_all(const float* __restrict__ x,
                                            const float* __restrict__ Wft,
                                            const int*   __restrict__ idx,
                                            const float* __restrict__ Wm,
                                            float* __restrict__ out,
                                            const float* __restrict__ gamma,
                                            const float* __restrict__ beta) {
    extern __shared__ float sm[];
    int*   sidxP = (int*)(sm + SIDX_OFF);
    float* feat  = sm + FEAT_OFF;
    const int tid  = threadIdx.x;
    const int wid  = tid >> 5;
    const int lane = tid & 31;
    const int bx   = blockIdx.x;

    const int P0  = bx * 256;
    const int b   = P0 >> 14;
    const int hw0 = P0 & (HW-1);

    // ================= P0: HMMA GEMM (0..127) | register-GJ inverse (128) =================
    if (bx == 128) {
        if (tid < 128) g_acc[ACC_BNSUM + tid] = 0.f;
        // ---- cov = Wm Wm^T into smem ----
        float* covs = sm;            // 4096
        float* colp = sm + 4096;     // 2 x 64 (double buffered)
        float* prow = sm + 4224;     // 2 x 136 (padded stride 17 per 16-col group)
        for (int e = tid; e < 4096; e += NT) {
            int i = e >> 6, j = e & 63;
            float s = 0.f;
            for (int c = 0; c < 64; c += 4) {
                float4 a  = *(const float4*)(Wm + i*64 + c);
                float4 bb = *(const float4*)(Wm + j*64 + c);
                s += a.x*bb.x + a.y*bb.y + a.z*bb.z + a.w*bb.w;
            }
            covs[e] = s;
        }
        __syncthreads();

        // ---- register-resident augmented matrix: row = tid>>3, 16 cols at (tid&7)*16 ----
        const int row = tid >> 3;          // 0..63
        const int c0  = (tid & 7) * 16;    // 0..112
        float a[16];
#pragma unroll
        for (int jj = 0; jj < 16; jj++) {
            int j = c0 + jj;
            a[jj] = (j < 64) ? covs[row*64 + j] : ((j - 64 == row) ? 1.f : 0.f);
        }
        // padded prow index: j + (j>>4)  (stride 17 per 16-group -> conflict-free)
        const int pbase = c0 + (c0 >> 4);

        for (int p = 0; p < 64; p++) {
            float* cb = colp + (p & 1) * 64;
            float* pb = prow + (p & 1) * 136;
            if (row == p) {
#pragma unroll
                for (int jj = 0; jj < 16; jj++) pb[pbase + jj] = a[jj];
            }
            if ((tid & 7) == (p >> 4)) cb[row] = a[p & 15];
            __syncthreads();
            float cp   = cb[row];
            float pinv = __fdividef(1.f, cb[p]);
            if (row == p) {
#pragma unroll
                for (int jj = 0; jj < 16; jj++) a[jj] = pb[pbase + jj] * pinv;
            } else {
#pragma unroll
                for (int jj = 0; jj < 16; jj++) {
                    float pr = pb[pbase + jj] * pinv;
                    a[jj] = fmaf(-cp, pr, a[jj]);
                }
            }
        }
        if (c0 >= 64) {
#pragma unroll
            for (int jj = 0; jj < 16; jj++)
                g_invcov[row*64 + (c0 - 64) + jj] = a[jj];
        }
    } else {
        float* scnt = sm + SCNT_OFF;
        char*  Ab   = (char*)sm + A_OFFB;
        char*  Bb   = (char*)sm + B_OFFB;
        const unsigned sbase = smem_u32(sm);
        const unsigned sA = sbase + A_OFFB;
        const unsigned sB = sbase + B_OFFB;

        if (tid < 64) {
            scnt[tid] = 0.f;
            ((int4*)sidxP)[tid] = ((const int4*)(idx + P0))[tid];
        }

        // ---- stage B = Wft [128 k][64 n] hi/lo bf16, chunk-swizzled ----
        for (int e4 = tid; e4 < 2048; e4 += NT) {
            int ch = e4 >> 4;
            int o4 = (e4 & 15) * 4;
            float4 v = ((const float4*)Wft)[e4];
            unsigned off = (unsigned)(ch*128)
                         + ((((unsigned)o4 >> 3) ^ (unsigned)(ch & 7)) << 4)
                         + (unsigned)((o4 & 7) * 2);
            __nv_bfloat162 h0 = __floats2bfloat162_rn(v.x, v.y);
            __nv_bfloat162 h1 = __floats2bfloat162_rn(v.z, v.w);
            __nv_bfloat162 l0 = __floats2bfloat162_rn(v.x - __bfloat162float(h0.x),
                                                      v.y - __bfloat162float(h0.y));
            __nv_bfloat162 l1 = __floats2bfloat162_rn(v.z - __bfloat162float(h1.x),
                                                      v.w - __bfloat162float(h1.y));
            *(uint2*)(Bb + off)         = make_uint2(*(uint32_t*)&h0, *(uint32_t*)&h1);
            *(uint2*)(Bb + B_LOB + off) = make_uint2(*(uint32_t*)&l0, *(uint32_t*)&l1);
        }

        // ---- warp tiling: 4x4 warps; warp = 32 px x 16 o ----
        const int wm = wid >> 2;
        const int wn = wid & 3;
        const int r  = lane & 7;
        const int g  = lane >> 3;
        unsigned aB0 = sA + (unsigned)((((g >> 1) * 8) + r) * 256)
                     + (unsigned)(((((wm*32 +  0) >> 3) + (g & 1)) ^ r) << 4);
        unsigned aB1 = sA + (unsigned)((((g >> 1) * 8) + r) * 256)
                     + (unsigned)(((((wm*32 + 16) >> 3) + (g & 1)) ^ r) << 4);
        unsigned bBs = sB + (unsigned)((((g & 1) * 8) + r) * 128)
                     + (unsigned)(((((wn*16) >> 3) + (g >> 1)) ^ r) << 4);

        const float* xb = x + (size_t)b*CIN*HW + hw0;

        for (int p = 0; p < 2; p++) {
            __syncthreads();
            const float* xgb = xb + p*128;
            for (int e4 = tid; e4 < 4096; e4 += NT) {
                int ch  = e4 >> 5;
                int px4 = (e4 & 31) * 4;
                float4 v = *(const float4*)(xgb + (size_t)ch*HW + px4);
                unsigned off = (unsigned)(ch*256)
                             + ((((unsigned)px4 >> 3) ^ (unsigned)(ch & 7)) << 4)
                             + (unsigned)((px4 & 7) * 2);
                __nv_bfloat162 h0 = __floats2bfloat162_rn(v.x, v.y);
                __nv_bfloat162 h1 = __floats2bfloat162_rn(v.z, v.w);
                __nv_bfloat162 l0 = __floats2bfloat162_rn(v.x - __bfloat162float(h0.x),
                                                          v.y - __bfloat162float(h0.y));
                __nv_bfloat162 l1 = __floats2bfloat162_rn(v.z - __bfloat162float(h1.x),
                                                          v.w - __bfloat162float(h1.y));
                *(uint2*)(Ab + off)         = make_uint2(*(uint32_t*)&h0, *(uint32_t*)&h1);
                *(uint2*)(Ab + A_LOB + off) = make_uint2(*(uint32_t*)&l0, *(uint32_t*)&l1);
            }
            __syncthreads();

            float acc[16];
#pragma unroll
            for (int i = 0; i < 16; i++) acc[i] = 0.f;
#pragma unroll
            for (int kk = 0; kk < 8; kk++) {
                uint32_t ah0[4], ah1[4], al0[4], al1[4], bh[4], bl[4];
                unsigned ka = (unsigned)kk * 4096u, kb = (unsigned)kk * 2048u;
                ldm4(ah0, aB0 + ka);
                ldm4(ah1, aB1 + ka);
                ldm4(al0, aB0 + A_LOB + ka);
                ldm4(al1, aB1 + A_LOB + ka);
                ldm4(bh,  bBs + kb);
                ldm4(bl,  bBs + B_LOB + kb);
                mma_bf16(acc + 0,  ah0, bh);
                mma_bf16(acc + 4,  ah0, bh + 2);
                mma_bf16(acc + 8,  ah1, bh);
                mma_bf16(acc + 12, ah1, bh + 2);
                mma_bf16(acc + 0,  ah0, bl);
                mma_bf16(acc + 4,  ah0, bl + 2);
                mma_bf16(acc + 8,  ah1, bl);
                mma_bf16(acc + 12, ah1, bl + 2);
                mma_bf16(acc + 0,  al0, bh);
                mma_bf16(acc + 4,  al0, bh + 2);
                mma_bf16(acc + 8,  al1, bh);
                mma_bf16(acc + 12, al1, bh + 2);
            }

            const int mrow = lane >> 2;
            const int ncol = (lane & 3) * 2;
#pragma unroll
            for (int mt = 0; mt < 2; mt++) {
#pragma unroll
                for (int nt = 0; nt < 2; nt++) {
                    float* a4 = acc + (mt*2 + nt)*4;
                    int o = wn*16 + nt*8 + ncol;
#pragma unroll
                    for (int half = 0; half < 2; half++) {
                        int pxl = p*128 + wm*32 + mt*16 + mrow + half*8;
                        float c0v = a4[half*2 + 0], c1v = a4[half*2 + 1];
                        *(float2*)(feat + pxl*FEAT_STR + o) = make_float2(c0v, c1v);
                        int k = sidxP[pxl];
                        red2(g_acc + ACC_SUMS + ((b*NK + k)*CO + o), c0v, c1v);
                        if (wn == 0 && nt == 0 && ncol == 0)
                            atomicAdd(&scnt[k], 1.f);
                    }
                }
            }
        }
        __syncthreads();
        if (tid < 64) atomicAdd(&g_acc[ACC_CNT + b*64 + tid], scnt[tid]);
    }
    gbar();

    // ================= P1: adjA (blocks 0..15) =================
    if (bx < 16) {
        float* As = sm;            // 4096
        float* mR = sm + 4096;     // 512
        float* tR = sm + 4608;     // 512
        const int ab = bx >> 3, r0 = (bx & 7) * 8;
        for (int e4 = tid; e4 < 1024; e4 += NT)
            ((float4*)As)[e4] = ((const float4*)g_invcov)[e4];
        for (int e = tid; e < 512; e += NT) {
            int rl = e >> 6;
            float c = g_acc[ACC_CNT + ab*64 + r0 + rl];
            float v = g_acc[ACC_SUMS + ab*4096 + r0*64 + e] / ((c > 0.f) ? c : 1.f);
            mR[e] = v;
            g_means[ab*4096 + r0*64 + e] = v;
        }
        __syncthreads();
        {
            int il = tid >> 6, j = tid & 63;
            float a = 0.f;
            for (int c = 0; c < 64; c++)
                a = fmaf(mR[il*64 + c], As[c*64 + j], a);
            tR[il*64 + j] = a;
            g_T[ab*4096 + (r0+il)*64 + j] = a;
        }
        __syncthreads();
        if (tid < 8) {
            float d = 0.f;
            for (int c = 0; c < 64; c++)
                d = fmaf(tR[tid*64 + c], mR[tid*64 + c], d);
            g_diag[ab*64 + r0 + tid] = d;
        }
    }
    gbar();

    // ================= P2: adjB (blocks 0..15) =================
    if (bx < 16) {
        float* Ms   = sm;          // 4096 swizzled means [c*64 + (j^(c&31))]
        float* tRb  = sm + 4096;   // 512
        float* sadj = sm + 4608;   // 512
        float* dg   = sm + 5120;   // 64
        const int ab = bx >> 3, r0 = (bx & 7) * 8;
        for (int e = tid; e < 4096; e += NT) {
            int j = e >> 6, c = e & 63;
            Ms[c*64 + (j ^ (c & 31))] = g_means[ab*4096 + e];
        }
        for (int e = tid; e < 512; e += NT)
            tRb[e] = g_T[ab*4096 + r0*64 + e];
        if (tid < 64) dg[tid] = g_diag[ab*64 + tid];
        __syncthreads();
        {
            int il = tid >> 6, j = tid & 63;
            float a = 0.f;
            for (int c = 0; c < 64; c++)
                a = fmaf(tRb[il*64 + c], Ms[c*64 + (j ^ (c & 31))], a);
            float q = dg[r0+il] + dg[j] - 2.f*a;
            sadj[il*64 + j] = expf(-sqrtf(fmaxf(q, 1e-12f)));
        }
        __syncthreads();
        {
            int il = tid >> 6, o = tid & 63;
            float a = 0.f;
            for (int jj = 0; jj < 64; jj++)
                a = fmaf(sadj[il*64 + jj], Ms[o*64 + (jj ^ (o & 31))], a);
            g_adjm[ab*4096 + (r0+il)*64 + o] = a;
        }
    }
    gbar();

    // ================= P3: features in smem + BN stats (blocks 0..127) =================
    if (bx < 128) {
        float* am4 = sm;           // 4096
        float* red = sm + 4096;    // 4096: s partials + q partials
        for (int e4 = tid; e4 < 1024; e4 += NT)
            ((float4*)am4)[e4] = ((const float4*)(g_adjm + b*4096))[e4];
        if (tid < 65) g_acc[bx*65 + tid] = 0.f;     // re-zero SUMS+CNT for next replay
        __syncthreads();

        const int pr = tid >> 4, c4 = tid & 15;
        float4 s4 = make_float4(0,0,0,0), q4 = make_float4(0,0,0,0);
#pragma unroll
        for (int it = 0; it < 8; it++) {
            int px = it*32 + pr;
            int k  = sidxP[px];
            float4* fp = (float4*)(feat + px*FEAT_STR + c4*4);
            float4 xv = *fp;
            float4 av = ((float4*)am4)[k*16 + c4];
            float v0 = fmaxf(xv.x+av.x, 0.f), v1 = fmaxf(xv.y+av.y, 0.f);
            float v2 = fmaxf(xv.z+av.z, 0.f), v3 = fmaxf(xv.w+av.w, 0.f);
            *fp = make_float4(v0, v1, v2, v3);
            s4.x += v0; s4.y += v1; s4.z += v2; s4.w += v3;
            q4.x += v0*v0; q4.y += v1*v1; q4.z += v2*v2; q4.w += v3*v3;
        }
        ((float4*)red)[pr*16 + c4] = s4;
        ((float4*)(red + 2048))[pr*16 + c4] = q4;
        __syncthreads();
        if (tid < 64) {
            float s = 0.f, q = 0.f;
#pragma unroll
            for (int p = 0; p < 32; p++) { s += red[p*64 + tid]; q += red[2048 + p*64 + tid]; }
            atomicAdd(&g_acc[ACC_BNSUM + tid], s);
            atomicAdd(&g_acc[ACC_BNSQ  + tid], q);
        }
    }
    gbar();

    // ================= P4: normalize from smem features, coalesced write =================
    if (bx < 128) {
        float* xts = sm;           // 2112  [o][px] padded 33
        float* ssc = sm + 2112;    // 64
        float* sbi = sm + 2176;    // 64
        if (tid < 64) {
            const float invN = 1.f/(float)NPIX;
            float mean = __ldcg(&g_acc[ACC_BNSUM + tid])*invN;
            float var  = __ldcg(&g_acc[ACC_BNSQ  + tid])*invN - mean*mean;
            float s = gamma[tid]*rsqrtf(var + 1e-5f);
            ssc[tid] = s; sbi[tid] = beta[tid] - mean*s;
        }
        __syncthreads();

        const int w = tid >> 5, ln = tid & 31;
        float sc4[4], bi4[4];
#pragma unroll
        for (int oo = 0; oo < 4; oo++) { sc4[oo] = ssc[w*4+oo]; bi4[oo] = sbi[w*4+oo]; }

        for (int st = 0; st < 8; st++) {
            __syncthreads();
            for (int e4 = tid; e4 < 512; e4 += NT) {
                int flat = e4*4, pxl = flat >> 6, o = flat & 63;
                float4 v = *(const float4*)(feat + (st*32 + pxl)*FEAT_STR + o);
                xts[(o+0)*33 + pxl] = v.x;
                xts[(o+1)*33 + pxl] = v.y;
                xts[(o+2)*33 + pxl] = v.z;
                xts[(o+3)*33 + pxl] = v.w;
            }
            __syncthreads();
            float* ob = out + (size_t)b*CO*HW + hw0 + st*32;
#pragma unroll
            for (int oo = 0; oo < 4; oo++) {
                int o = w*4 + oo;
                ob[(size_t)o*HW + ln] = fmaf(xts[o*33 + ln], sc4[oo], bi4[oo]);
            }
        }
    }
}

// ---------------- launch ----------------
extern "C" void kernel_launch(void* const* d_in, const int* in_sizes, int n_in,
                              void* d_out, int out_size) {
    const float* x     = (const float*)d_in[0];
    const int*   index = (const int*)  d_in[1];
    const float* Wft   = (const float*)d_in[2];
    const float* Wm    = (const float*)d_in[3];
    const float* gamma = (const float*)d_in[4];
    const float* beta  = (const float*)d_in[5];
    float* out = (float*)d_out;

    cudaFuncSetAttribute(k_all, cudaFuncAttributeMaxDynamicSharedMemorySize, SMEM_BYTES);
    k_all<<<GRIDN, NT, SMEM_BYTES>>>(x, Wft, index, Wm, out, gamma, beta);
}

// round 14
// speedup vs baseline: 2.3476x; 2.3476x over previous
#include <cuda_runtime.h>
#include <cuda_bf16.h>
#include <cstdint>

#define HW   16384
#define NB   2
#define CIN  128
#define CO   64
#define NK   64
#define NPIX (NB*HW)
#define GRIDN 129u
#define NT    512

// accumulator pack
#define ACC_SUMS  0        // 8192 floats: [b][k][o]
#define ACC_CNT   8192     // 128 floats:  [b][k]
#define ACC_BNSUM 8320     // 64
#define ACC_BNSQ  8384     // 64
#define ACCN      8448

// smem layout
// bytes: A tiles @1024 (hi 32KB, lo 32KB -> 64KB), B @66560 (hi 16KB, lo 16KB)
// floats: scnt @24832, sidx @24896 (256 ints), feat @25152
#define A_OFFB    1024
#define A_LOB     32768
#define B_OFFB    66560
#define B_LOB     16384
#define SCNT_OFF  24832
#define SIDX_OFF  24896
#define FEAT_OFF  25152
#define FEAT_STR  68
#define SMEM_FLOATS (FEAT_OFF + 256*FEAT_STR)    // 42560
#define SMEM_BYTES  (SMEM_FLOATS*4)              // 170240

// ---------------- scratch (static device globals; zero-initialized by loader) ----------------
__device__ float    g_acc[ACCN];
__device__ unsigned g_bar;                   // monotonic ticket barrier
__device__ float    g_invcov[CO*CO];
__device__ float    g_means[NB*NK*CO];
__device__ float    g_T[NB*NK*CO];
__device__ float    g_diag[NB*NK];
__device__ float    g_adjm[NB*NK*CO];

// ---------------- helpers ----------------
__device__ __forceinline__ unsigned smem_u32(const void* p) {
    unsigned a;
    asm("{ .reg .u64 t; cvta.to.shared.u64 t, %1; cvt.u32.u64 %0, t; }" : "=r"(a) : "l"(p));
    return a;
}
__device__ __forceinline__ void ldm4(uint32_t* r, unsigned addr) {
    asm volatile("ldmatrix.sync.aligned.m8n8.x4.trans.shared.b16 {%0,%1,%2,%3}, [%4];"
                 : "=r"(r[0]), "=r"(r[1]), "=r"(r[2]), "=r"(r[3]) : "r"(addr));
}
__device__ __forceinline__ void mma_bf16(float* c, const uint32_t* a, const uint32_t* bb) {
    asm volatile("mma.sync.aligned.m16n8k16.row.col.f32.bf16.bf16.f32 "
                 "{%0,%1,%2,%3}, {%4,%5,%6,%7}, {%8,%9}, {%0,%1,%2,%3};"
                 : "+f"(c[0]), "+f"(c[1]), "+f"(c[2]), "+f"(c[3])
                 : "r"(a[0]), "r"(a[1]), "r"(a[2]), "r"(a[3]), "r"(bb[0]), "r"(bb[1]));
}
__device__ __forceinline__ void red2(float* p, float a, float b) {
    asm volatile("red.add.v2.f32 [%0], {%1, %2};" :: "l"(p), "f"(a), "f"(b) : "memory");
}

// device-wide ticket barrier; all GRIDN blocks resident, monotonic across replays
__device__ __forceinline__ void gbar() {
    __threadfence();
    __syncthreads();
    if (threadIdx.x == 0) {
        unsigned t   = atomicAdd(&g_bar, 1u);
        unsigned tgt = (t / GRIDN + 1u) * GRIDN;
        unsigned v;
        for (;;) {
            asm volatile("ld.acquire.gpu.u32 %0, [%1];" : "=r"(v) : "l"(&g_bar) : "memory");
            if (v >= tgt) break;
            __nanosleep(32);
        }
    }
    __syncthreads();
}

// ---------------- the single fused kernel ----------------
__global__ __launch_bounds__(NT) void k_all(const float* __restrict__ x,
                                            const float* __restrict__ Wft,
                                            const int*   __restrict__ idx,
                                            const float* __restrict__ Wm,
                                            float* __restrict__ out,
                                            const float* __restrict__ gamma,
                                            const float* __restrict__ beta) {
    extern __shared__ float sm[];
    int*   sidxP = (int*)(sm + SIDX_OFF);
    float* feat  = sm + FEAT_OFF;
    const int tid  = threadIdx.x;
    const int wid  = tid >> 5;
    const int lane = tid & 31;
    const int bx   = blockIdx.x;

    const int P0  = bx * 256;
    const int b   = P0 >> 14;
    const int hw0 = P0 & (HW-1);

    // ================= P0: HMMA GEMM (0..127) | static-unrolled register-GJ inverse (128) =================
    if (bx == 128) {
        if (tid < 128) g_acc[ACC_BNSUM + tid] = 0.f;
        // ---- cov = Wm Wm^T into smem ----
        float* covs = sm;            // 4096
        float* colp = sm + 4096;     // 2 x 64 (double buffered)
        float* prow = sm + 4224;     // 2 x 136 (padded stride 17 per 16-col group)
        for (int e = tid; e < 4096; e += NT) {
            int i = e >> 6, j = e & 63;
            float s = 0.f;
            for (int c = 0; c < 64; c += 4) {
                float4 a  = *(const float4*)(Wm + i*64 + c);
                float4 bb = *(const float4*)(Wm + j*64 + c);
                s += a.x*bb.x + a.y*bb.y + a.z*bb.z + a.w*bb.w;
            }
            covs[e] = s;
        }
        __syncthreads();

        // ---- register-resident augmented matrix: row = tid>>3, 16 cols at (tid&7)*16 ----
        const int row = tid >> 3;          // 0..63
        const int cg  = tid & 7;           // col group 0..7
        const int c0  = cg * 16;           // 0..112
        float a[16];
#pragma unroll
        for (int jj = 0; jj < 16; jj++) {
            int j = c0 + jj;
            a[jj] = (j < 64) ? covs[row*64 + j] : ((j - 64 == row) ? 1.f : 0.f);
        }
        const int pbase = cg * 17;         // padded stride-17 per 16-col group

        for (int pg = 0; pg < 4; pg++) {   // pivot groups of 16; inner fully unrolled
#pragma unroll
            for (int pi = 0; pi < 16; pi++) {
                const int p = pg*16 + pi;
                float* cb = colp + (pi & 1) * 64;
                float* pb = prow + (pi & 1) * 136;
                if (row == p) {
#pragma unroll
                    for (int jj = 0; jj < 16; jj++) pb[pbase + jj] = a[jj];
                }
                if (cg == pg) cb[row] = a[pi];       // static register index
                __syncthreads();
                float cp   = cb[row];
                float pinv = __fdividef(1.f, cb[p]);
                if (row == p) {
#pragma unroll
                    for (int jj = 0; jj < 16; jj++) a[jj] = pb[pbase + jj] * pinv;
                } else {
#pragma unroll
                    for (int jj = 0; jj < 16; jj++)
                        a[jj] = fmaf(-cp, pb[pbase + jj] * pinv, a[jj]);
                }
            }
        }
        if (c0 >= 64) {
#pragma unroll
            for (int jj = 0; jj < 16; jj++)
                g_invcov[row*64 + (c0 - 64) + jj] = a[jj];
        }
    } else {
        float* scnt = sm + SCNT_OFF;
        char*  Ab   = (char*)sm + A_OFFB;
        char*  Bb   = (char*)sm + B_OFFB;
        const unsigned sbase = smem_u32(sm);
        const unsigned sA = sbase + A_OFFB;
        const unsigned sB = sbase + B_OFFB;

        if (tid < 64) {
            scnt[tid] = 0.f;
            ((int4*)sidxP)[tid] = ((const int4*)(idx + P0))[tid];
        }

        // ---- stage B = Wft [128 k][64 n] hi/lo bf16, chunk-swizzled ----
        for (int e4 = tid; e4 < 2048; e4 += NT) {
            int ch = e4 >> 4;
            int o4 = (e4 & 15) * 4;
            float4 v = ((const float4*)Wft)[e4];
            unsigned off = (unsigned)(ch*128)
                         + ((((unsigned)o4 >> 3) ^ (unsigned)(ch & 7)) << 4)
                         + (unsigned)((o4 & 7) * 2);
            __nv_bfloat162 h0 = __floats2bfloat162_rn(v.x, v.y);
            __nv_bfloat162 h1 = __floats2bfloat162_rn(v.z, v.w);
            __nv_bfloat162 l0 = __floats2bfloat162_rn(v.x - __bfloat162float(h0.x),
                                                      v.y - __bfloat162float(h0.y));
            __nv_bfloat162 l1 = __floats2bfloat162_rn(v.z - __bfloat162float(h1.x),
                                                      v.w - __bfloat162float(h1.y));
            *(uint2*)(Bb + off)         = make_uint2(*(uint32_t*)&h0, *(uint32_t*)&h1);
            *(uint2*)(Bb + B_LOB + off) = make_uint2(*(uint32_t*)&l0, *(uint32_t*)&l1);
        }

        // ---- warp tiling: 4x4 warps; warp = 32 px x 16 o ----
        const int wm = wid >> 2;
        const int wn = wid & 3;
        const int r  = lane & 7;
        const int g  = lane >> 3;
        unsigned aB0 = sA + (unsigned)((((g >> 1) * 8) + r) * 256)
                     + (unsigned)(((((wm*32 +  0) >> 3) + (g & 1)) ^ r) << 4);
        unsigned aB1 = sA + (unsigned)((((g >> 1) * 8) + r) * 256)
                     + (unsigned)(((((wm*32 + 16) >> 3) + (g & 1)) ^ r) << 4);
        unsigned bBs = sB + (unsigned)((((g & 1) * 8) + r) * 128)
                     + (unsigned)(((((wn*16) >> 3) + (g >> 1)) ^ r) << 4);

        const float* xb = x + (size_t)b*CIN*HW + hw0;

        for (int p = 0; p < 2; p++) {
            __syncthreads();
            const float* xgb = xb + p*128;
            for (int e4 = tid; e4 < 4096; e4 += NT) {
                int ch  = e4 >> 5;
                int px4 = (e4 & 31) * 4;
                float4 v = *(const float4*)(xgb + (size_t)ch*HW + px4);
                unsigned off = (unsigned)(ch*256)
                             + ((((unsigned)px4 >> 3) ^ (unsigned)(ch & 7)) << 4)
                             + (unsigned)((px4 & 7) * 2);
                __nv_bfloat162 h0 = __floats2bfloat162_rn(v.x, v.y);
                __nv_bfloat162 h1 = __floats2bfloat162_rn(v.z, v.w);
                __nv_bfloat162 l0 = __floats2bfloat162_rn(v.x - __bfloat162float(h0.x),
                                                          v.y - __bfloat162float(h0.y));
                __nv_bfloat162 l1 = __floats2bfloat162_rn(v.z - __bfloat162float(h1.x),
                                                          v.w - __bfloat162float(h1.y));
                *(uint2*)(Ab + off)         = make_uint2(*(uint32_t*)&h0, *(uint32_t*)&h1);
                *(uint2*)(Ab + A_LOB + off) = make_uint2(*(uint32_t*)&l0, *(uint32_t*)&l1);
            }
            __syncthreads();

            float acc[16];
#pragma unroll
            for (int i = 0; i < 16; i++) acc[i] = 0.f;
#pragma unroll
            for (int kk = 0; kk < 8; kk++) {
                uint32_t ah0[4], ah1[4], al0[4], al1[4], bh[4], bl[4];
                unsigned ka = (unsigned)kk * 4096u, kb = (unsigned)kk * 2048u;
                ldm4(ah0, aB0 + ka);
                ldm4(ah1, aB1 + ka);
                ldm4(al0, aB0 + A_LOB + ka);
                ldm4(al1, aB1 + A_LOB + ka);
                ldm4(bh,  bBs + kb);
                ldm4(bl,  bBs + B_LOB + kb);
                mma_bf16(acc + 0,  ah0, bh);
                mma_bf16(acc + 4,  ah0, bh + 2);
                mma_bf16(acc + 8,  ah1, bh);
                mma_bf16(acc + 12, ah1, bh + 2);
                mma_bf16(acc + 0,  ah0, bl);
                mma_bf16(acc + 4,  ah0, bl + 2);
                mma_bf16(acc + 8,  ah1, bl);
                mma_bf16(acc + 12, ah1, bl + 2);
                mma_bf16(acc + 0,  al0, bh);
                mma_bf16(acc + 4,  al0, bh + 2);
                mma_bf16(acc + 8,  al1, bh);
                mma_bf16(acc + 12, al1, bh + 2);
            }

            const int mrow = lane >> 2;
            const int ncol = (lane & 3) * 2;
#pragma unroll
            for (int mt = 0; mt < 2; mt++) {
#pragma unroll
                for (int nt = 0; nt < 2; nt++) {
                    float* a4 = acc + (mt*2 + nt)*4;
                    int o = wn*16 + nt*8 + ncol;
#pragma unroll
                    for (int half = 0; half < 2; half++) {
                        int pxl = p*128 + wm*32 + mt*16 + mrow + half*8;
                        float c0v = a4[half*2 + 0], c1v = a4[half*2 + 1];
                        *(float2*)(feat + pxl*FEAT_STR + o) = make_float2(c0v, c1v);
                        int k = sidxP[pxl];
                        red2(g_acc + ACC_SUMS + ((b*NK + k)*CO + o), c0v, c1v);
                        if (wn == 0 && nt == 0 && ncol == 0)
                            atomicAdd(&scnt[k], 1.f);
                    }
                }
            }
        }
        __syncthreads();
        if (tid < 64) atomicAdd(&g_acc[ACC_CNT + b*64 + tid], scnt[tid]);
    }
    gbar();

    // ================= P1: adjA (blocks 0..15) =================
    if (bx < 16) {
        float* As = sm;            // 4096
        float* mR = sm + 4096;     // 512
        float* tR = sm + 4608;     // 512
        const int ab = bx >> 3, r0 = (bx & 7) * 8;
        for (int e4 = tid; e4 < 1024; e4 += NT)
            ((float4*)As)[e4] = ((const float4*)g_invcov)[e4];
        for (int e = tid; e < 512; e += NT) {
            int rl = e >> 6;
            float c = g_acc[ACC_CNT + ab*64 + r0 + rl];
            float v = g_acc[ACC_SUMS + ab*4096 + r0*64 + e] / ((c > 0.f) ? c : 1.f);
            mR[e] = v;
            g_means[ab*4096 + r0*64 + e] = v;
        }
        __syncthreads();
        {
            int il = tid >> 6, j = tid & 63;
            float a = 0.f;
            for (int c = 0; c < 64; c++)
                a = fmaf(mR[il*64 + c], As[c*64 + j], a);
            tR[il*64 + j] = a;
            g_T[ab*4096 + (r0+il)*64 + j] = a;
        }
        __syncthreads();
        if (tid < 8) {
            float d = 0.f;
            for (int c = 0; c < 64; c++)
                d = fmaf(tR[tid*64 + c], mR[tid*64 + c], d);
            g_diag[ab*64 + r0 + tid] = d;
        }
    }
    gbar();

    // ================= P2: adjB (blocks 0..15) =================
    if (bx < 16) {
        float* Ms   = sm;          // 4096 swizzled means [c*64 + (j^(c&31))]
        float* tRb  = sm + 4096;   // 512
        float* sadj = sm + 4608;   // 512
        float* dg   = sm + 5120;   // 64
        const int ab = bx >> 3, r0 = (bx & 7) * 8;
        for (int e = tid; e < 4096; e += NT) {
            int j = e >> 6, c = e & 63;
            Ms[c*64 + (j ^ (c & 31))] = g_means[ab*4096 + e];
        }
        for (int e = tid; e < 512; e += NT)
            tRb[e] = g_T[ab*4096 + r0*64 + e];
        if (tid < 64) dg[tid] = g_diag[ab*64 + tid];
        __syncthreads();
        {
            int il = tid >> 6, j = tid & 63;
            float a = 0.f;
            for (int c = 0; c < 64; c++)
                a = fmaf(tRb[il*64 + c], Ms[c*64 + (j ^ (c & 31))], a);
            float q = dg[r0+il] + dg[j] - 2.f*a;
            sadj[il*64 + j] = expf(-sqrtf(fmaxf(q, 1e-12f)));
        }
        __syncthreads();
        {
            int il = tid >> 6, o = tid & 63;
            float a = 0.f;
            for (int jj = 0; jj < 64; jj++)
                a = fmaf(sadj[il*64 + jj], Ms[o*64 + (jj ^ (o & 31))], a);
            g_adjm[ab*4096 + (r0+il)*64 + o] = a;
        }
    }
    gbar();

    // ================= P3: features in smem + BN stats (blocks 0..127) =================
    if (bx < 128) {
        float* am4 = sm;           // 4096
        float* red = sm + 4096;    // 4096: s partials + q partials
        for (int e4 = tid; e4 < 1024; e4 += NT)
            ((float4*)am4)[e4] = ((const float4*)(g_adjm + b*4096))[e4];
        if (tid < 65) g_acc[bx*65 + tid] = 0.f;     // re-zero SUMS+CNT for next replay
        __syncthreads();

        const int pr = tid >> 4, c4 = tid & 15;
        float4 s4 = make_float4(0,0,0,0), q4 = make_float4(0,0,0,0);
#pragma unroll
        for (int it = 0; it < 8; it++) {
            int px = it*32 + pr;
            int k  = sidxP[px];
            float4* fp = (float4*)(feat + px*FEAT_STR + c4*4);
            float4 xv = *fp;
            float4 av = ((float4*)am4)[k*16 + c4];
            float v0 = fmaxf(xv.x+av.x, 0.f), v1 = fmaxf(xv.y+av.y, 0.f);
            float v2 = fmaxf(xv.z+av.z, 0.f), v3 = fmaxf(xv.w+av.w, 0.f);
            *fp = make_float4(v0, v1, v2, v3);
            s4.x += v0; s4.y += v1; s4.z += v2; s4.w += v3;
            q4.x += v0*v0; q4.y += v1*v1; q4.z += v2*v2; q4.w += v3*v3;
        }
        ((float4*)red)[pr*16 + c4] = s4;
        ((float4*)(red + 2048))[pr*16 + c4] = q4;
        __syncthreads();
        if (tid < 64) {
            float s = 0.f, q = 0.f;
#pragma unroll
            for (int p = 0; p < 32; p++) { s += red[p*64 + tid]; q += red[2048 + p*64 + tid]; }
            atomicAdd(&g_acc[ACC_BNSUM + tid], s);
            atomicAdd(&g_acc[ACC_BNSQ  + tid], q);
        }
    }
    gbar();

    // ================= P4: normalize from smem features, coalesced write =================
    if (bx < 128) {
        float* xts = sm;           // 2112  [o][px] padded 33
        float* ssc = sm + 2112;    // 64
        float* sbi = sm + 2176;    // 64
        if (tid < 64) {
            const float invN = 1.f/(float)NPIX;
            float mean = __ldcg(&g_acc[ACC_BNSUM + tid])*invN;
            float var  = __ldcg(&g_acc[ACC_BNSQ  + tid])*invN - mean*mean;
            float s = gamma[tid]*rsqrtf(var + 1e-5f);
            ssc[tid] = s; sbi[tid] = beta[tid] - mean*s;
        }
        __syncthreads();

        const int w = tid >> 5, ln = tid & 31;
        float sc4[4], bi4[4];
#pragma unroll
        for (int oo = 0; oo < 4; oo++) { sc4[oo] = ssc[w*4+oo]; bi4[oo] = sbi[w*4+oo]; }

        for (int st = 0; st < 8; st++) {
            __syncthreads();
            for (int e4 = tid; e4 < 512; e4 += NT) {
                int flat = e4*4, pxl = flat >> 6, o = flat & 63;
                float4 v = *(const float4*)(feat + (st*32 + pxl)*FEAT_STR + o);
                xts[(o+0)*33 + pxl] = v.x;
                xts[(o+1)*33 + pxl] = v.y;
                xts[(o+2)*33 + pxl] = v.z;
                xts[(o+3)*33 + pxl] = v.w;
            }
            __syncthreads();
            float* ob = out + (size_t)b*CO*HW + hw0 + st*32;
#pragma unroll
            for (int oo = 0; oo < 4; oo++) {
                int o = w*4 + oo;
                ob[(size_t)o*HW + ln] = fmaf(xts[o*33 + ln], sc4[oo], bi4[oo]);
            }
        }
    }
}

// ---------------- launch ----------------
extern "C" void kernel_launch(void* const* d_in, const int* in_sizes, int n_in,
                              void* d_out, int out_size) {
    const float* x     = (const float*)d_in[0];
    const int*   index = (const int*)  d_in[1];
    const float* Wft   = (const float*)d_in[2];
    const float* Wm    = (const float*)d_in[3];
    const float* gamma = (const float*)d_in[4];
    const float* beta  = (const float*)d_in[5];
    float* out = (float*)d_out;

    cudaFuncSetAttribute(k_all, cudaFuncAttributeMaxDynamicSharedMemorySize, SMEM_BYTES);
    k_all<<<GRIDN, NT, SMEM_BYTES>>>(x, Wft, index, Wm, out, gamma, beta);
}